// round 13
// baseline (speedup 1.0000x reference)
#include <cuda_runtime.h>
#include <cuda_fp16.h>
#include <math_constants.h>
#include <cstdint>

// Shapes
#define BB 4
#define TQ 1024
#define DMODEL 2048
#define NHEADS 16
#define HDIM 128
#define CACHE 1024
#define MROWS (BB*TQ)          // 4096
#define INV_SCALE 0.08838834764831843f  // 1/sqrt(128)

#define OUT_ELEMS   (BB*TQ*DMODEL)
#define NEWK_OFF    OUT_ELEMS
#define NEWV_OFF    (OUT_ELEMS + BB*2048*DMODEL)

// Scratch
__device__ __half g_qph  [MROWS*DMODEL];          // Q proj (fp16, pre-scaled)
__device__ __half g_attnh[MROWS*DMODEL];          // attention out (fp16)
__device__ __half g_qh [MROWS*DMODEL];            // fp16 activations
__device__ __half g_kh [MROWS*DMODEL];
__device__ __half g_vh [MROWS*DMODEL];
__device__ __half g_ckh[BB*CACHE*DMODEL];         // fp16 K cache [b][t][d]
__device__ __half g_cvt[BB*NHEADS*HDIM*CACHE];    // fp16 V cache transposed [bh][d][t]
__device__ __half g_wqh[DMODEL*DMODEL];           // fp16 weights
__device__ __half g_wkh[DMODEL*DMODEL];
__device__ __half g_wvh[DMODEL*DMODEL];
__device__ __half g_woh[DMODEL*DMODEL];

__device__ __forceinline__ uint32_t smem_u32(const void* p) {
    uint32_t a;
    asm("{ .reg .u64 t; cvta.to.shared.u64 t, %1; cvt.u32.u64 %0, t; }"
        : "=r"(a) : "l"(p));
    return a;
}
__device__ __forceinline__ void cp_async16(uint32_t dst, const void* src) {
    asm volatile("cp.async.cg.shared.global [%0], [%1], 16;" :: "r"(dst), "l"(src));
}
#define CP_COMMIT() asm volatile("cp.async.commit_group;" ::: "memory")
#define CP_WAIT2()  asm volatile("cp.async.wait_group 2;" ::: "memory")
#define CP_WAIT0()  asm volatile("cp.async.wait_group 0;" ::: "memory")

__device__ __forceinline__ void mma_f16(float& d0, float& d1, float& d2, float& d3,
                                        uint32_t a0, uint32_t a1, uint32_t a2, uint32_t a3,
                                        uint32_t b0, uint32_t b1)
{
    asm volatile(
        "mma.sync.aligned.m16n8k16.row.col.f32.f16.f16.f32 "
        "{%0,%1,%2,%3}, {%4,%5,%6,%7}, {%8,%9}, {%0,%1,%2,%3};"
        : "+f"(d0), "+f"(d1), "+f"(d2), "+f"(d3)
        : "r"(a0), "r"(a1), "r"(a2), "r"(a3), "r"(b0), "r"(b1));
}

// ===========================================================================
// prep kernels
// ===========================================================================
__global__ void conv4_kernel(const float* i0, __half* o0, const float* i1, __half* o1,
                             const float* i2, __half* o2, const float* i3, __half* o3)
{
    int idx = blockIdx.x * blockDim.x + threadIdx.x;
    const float* in; __half* out;
    switch (blockIdx.y) {
        case 0: in = i0; out = o0; break;
        case 1: in = i1; out = o1; break;
        case 2: in = i2; out = o2; break;
        default: in = i3; out = o3; break;
    }
    float4 v0 = ((const float4*)in)[2*idx];
    float4 v1 = ((const float4*)in)[2*idx+1];
    __half2 h[4];
    h[0] = __floats2half2_rn(v0.x, v0.y);
    h[1] = __floats2half2_rn(v0.z, v0.w);
    h[2] = __floats2half2_rn(v1.x, v1.y);
    h[3] = __floats2half2_rn(v1.z, v1.w);
    ((uint4*)out)[idx] = *(const uint4*)h;
}

// V cache: fp32 [b][t][2048] -> fp16 transposed per head [bh][d (128)][t (1024)]
__global__ void transpose_v_kernel(const float* __restrict__ cachev,
                                   __half* __restrict__ vt)
{
    __shared__ float tile[32][33];
    const int tx = threadIdx.x, ty = threadIdx.y;   // (32, 8)
    const int t0 = blockIdx.x * 32;
    const int d0 = blockIdx.y * 32;
    const int bh = blockIdx.z;
    const int b = bh >> 4, h = bh & 15;
#pragma unroll
    for (int dt = 0; dt < 4; dt++) {
        int t = t0 + ty + dt*8;
        tile[ty + dt*8][tx] =
            cachev[((size_t)b*CACHE + t)*DMODEL + h*HDIM + d0 + tx];
    }
    __syncthreads();
#pragma unroll
    for (int dt = 0; dt < 4; dt++) {
        int d = d0 + ty + dt*8;
        vt[(size_t)bh*HDIM*CACHE + (size_t)d*CACHE + t0 + tx] =
            __float2half_rn(tile[tx][ty + dt*8]);
    }
}

// ===========================================================================
// fp16 mma.sync GEMM: CTA 128x256, warp tile 64x64, BK=64 (fp16), 4-stage
// cp.async, single barrier per k-iter, register double-buffered fragments.
// ===========================================================================
#define BK 64
#define STAGES 4
#define RS32 36
#define STAGE_ROWS 384
#define STAGE_U32 (STAGE_ROWS*RS32)
#define STAGE_BYTES (STAGE_U32*4)
#define GEMM_SMEM  (STAGES*STAGE_BYTES)       // 221184
#define NITERS (2048/BK)                      // 32

// out_mode: 0 = fp32 store, 1 = fp16 store (scaled), 2 = permuted fp32 scatter
struct GemmSet { const __half *A, *W; const float* bias; void *C; float scale; int out_mode; };

__global__ __launch_bounds__(256, 1)
void gemm_f16(GemmSet s0, GemmSet s1, GemmSet s2)
{
    const GemmSet& S = (blockIdx.z == 0) ? s0 : (blockIdx.z == 1) ? s1 : s2;
    const __half* __restrict__ A = S.A;
    const __half* __restrict__ W = S.W;
    const float* __restrict__ bias = S.bias;

    extern __shared__ __align__(128) uint32_t smem[];
    const uint32_t smem_addr = smem_u32(smem);
    const int tid  = threadIdx.x;
    const int wid  = tid >> 5;
    const int lane = tid & 31;
    const int bm = blockIdx.y * 128;
    const int bn = blockIdx.x * 256;
    const int wm = (wid & 1) * 64;
    const int wn = (wid >> 1) * 64;

    auto load_stage = [&](int it) {
        const int s  = it & (STAGES - 1);
        const int k0 = it * BK;
        const uint32_t sbase = smem_addr + s * STAGE_BYTES;
        const __half* Ab = A + (size_t)bm * 2048 + k0;
        const __half* Wb = W + (size_t)bn * 2048 + k0;
#pragma unroll
        for (int c = 0; c < 4; c++) {
            int id = tid + c * 256;
            int row = id >> 3, seg = id & 7;
            cp_async16(sbase + (row * RS32 + seg * 4) * 4,
                       Ab + (size_t)row * 2048 + seg * 8);
        }
#pragma unroll
        for (int c = 0; c < 8; c++) {
            int id = tid + c * 256;
            int row = id >> 3, seg = id & 7;
            cp_async16(sbase + ((128 + row) * RS32 + seg * 4) * 4,
                       Wb + (size_t)row * 2048 + seg * 8);
        }
    };

    float acc[4][8][4];
#pragma unroll
    for (int mf = 0; mf < 4; mf++)
#pragma unroll
        for (int nf = 0; nf < 8; nf++)
#pragma unroll
            for (int r = 0; r < 4; r++) acc[mf][nf][r] = 0.f;

    load_stage(0); CP_COMMIT();
    load_stage(1); CP_COMMIT();
    load_stage(2); CP_COMMIT();

    const int lr = lane >> 2;
    const int lc = lane & 3;

    uint32_t afr[2][4][4], bfr[2][8][2];

    auto load_frags = [&](const uint32_t* As32, const uint32_t* Bs32, int ks,
                          uint32_t (&af)[4][4], uint32_t (&bf)[8][2]) {
        const int kb = ks * 8;
#pragma unroll
        for (int nf = 0; nf < 8; nf++) {
            const uint32_t* bp = Bs32 + (wn + nf*8 + lr) * RS32 + kb + lc;
            bf[nf][0] = bp[0];
            bf[nf][1] = bp[4];
        }
#pragma unroll
        for (int mf = 0; mf < 4; mf++) {
            const uint32_t* ap = As32 + (wm + mf*16 + lr) * RS32 + kb + lc;
            af[mf][0] = ap[0];
            af[mf][1] = ap[8*RS32];
            af[mf][2] = ap[4];
            af[mf][3] = ap[8*RS32 + 4];
        }
    };

    for (int i = 0; i < NITERS; i++) {
        CP_WAIT2();
        __syncthreads();
        if (i + 3 < NITERS) load_stage(i + 3);
        CP_COMMIT();

        const uint32_t* As32 = smem + (size_t)(i & (STAGES-1)) * STAGE_U32;
        const uint32_t* Bs32 = As32 + 128 * RS32;

        load_frags(As32, Bs32, 0, afr[0], bfr[0]);
#pragma unroll
        for (int ks = 0; ks < 4; ks++) {
            const int cur = ks & 1;
            if (ks < 3) load_frags(As32, Bs32, ks + 1, afr[cur^1], bfr[cur^1]);
#pragma unroll
            for (int mf = 0; mf < 4; mf++)
#pragma unroll
                for (int nf = 0; nf < 8; nf++)
                    mma_f16(acc[mf][nf][0], acc[mf][nf][1],
                            acc[mf][nf][2], acc[mf][nf][3],
                            afr[cur][mf][0], afr[cur][mf][1],
                            afr[cur][mf][2], afr[cur][mf][3],
                            bfr[cur][nf][0], bfr[cur][nf][1]);
        }
    }

    if (S.out_mode == 2) {
        float* C = (float*)S.C;
#pragma unroll
        for (int nf = 0; nf < 8; nf++) {
            const int col = bn + wn + nf*8 + lc*2;
            const float b0 = bias[col], b1 = bias[col + 1];
            const int ch = (col >> 7) << 7;
            const int cl = col & 127;
#pragma unroll
            for (int mf = 0; mf < 4; mf++) {
                const int row0 = bm + wm + mf*16 + lr;
#pragma unroll
                for (int rr = 0; rr < 2; rr++) {
                    const int row = row0 + rr*8;
                    const int bb = row >> 10, tq = row & 1023;
                    const int ii = ch | 64 | (tq >> 4);
                    const int jj = ((tq & 15) << 7) | cl;
                    *(float2*)(C + (((size_t)((bb << 11) | ii)) << 11) + jj) =
                        make_float2(acc[mf][nf][rr*2+0] + b0,
                                    acc[mf][nf][rr*2+1] + b1);
                }
            }
        }
    } else if (S.out_mode == 1) {
        __half* C = (__half*)S.C;
        const float scale = S.scale;
#pragma unroll
        for (int nf = 0; nf < 8; nf++) {
            const int col = bn + wn + nf*8 + lc*2;
            const float b0 = bias[col], b1 = bias[col + 1];
#pragma unroll
            for (int mf = 0; mf < 4; mf++) {
                const int row0 = bm + wm + mf*16 + lr;
                *(__half2*)(C + (size_t)row0 * 2048 + col) =
                    __floats2half2_rn((acc[mf][nf][0] + b0) * scale,
                                      (acc[mf][nf][1] + b1) * scale);
                *(__half2*)(C + (size_t)(row0 + 8) * 2048 + col) =
                    __floats2half2_rn((acc[mf][nf][2] + b0) * scale,
                                      (acc[mf][nf][3] + b1) * scale);
            }
        }
    } else {
        float* C = (float*)S.C;
#pragma unroll
        for (int nf = 0; nf < 8; nf++) {
            const int col = bn + wn + nf*8 + lc*2;
            const float b0 = bias[col], b1 = bias[col + 1];
#pragma unroll
            for (int mf = 0; mf < 4; mf++) {
                const int row0 = bm + wm + mf*16 + lr;
                *(float2*)(C + (size_t)row0 * 2048 + col) =
                    make_float2(acc[mf][nf][0] + b0, acc[mf][nf][1] + b1);
                *(float2*)(C + (size_t)(row0 + 8) * 2048 + col) =
                    make_float2(acc[mf][nf][2] + b0, acc[mf][nf][3] + b1);
            }
        }
    }
}

// ===========================================================================
// fp16 tensor-core flash attention, causal over cache only. (unchanged)
// ===========================================================================
#define QST 68
#define VST 36
#define AQS 0
#define AKS (64*QST)
#define AKSZ (64*QST)
#define AVTS (AKS + 2*AKSZ)
#define AVSZ (128*VST)
#define APS (AVTS + 2*AVSZ)
#define ATTN_U32 (APS + 64*VST)            // 24576 -> 98304 B

__global__ __launch_bounds__(128, 1)
void attn_mma(const __half* __restrict__ Q,
              const __half* __restrict__ K,
              const __half* __restrict__ Vt,
              __half* __restrict__ O)
{
    extern __shared__ __align__(128) uint32_t sm[];
    const uint32_t smaddr = smem_u32(sm);
    const int tid = threadIdx.x;
    const int w = tid >> 5, lane = tid & 31;
    const int lr = lane >> 2, lc = lane & 3;
    const int qb = gridDim.x - 1 - blockIdx.x;   // big tiles first
    const int bh = blockIdx.y;
    const int b = bh >> 4, h = bh & 15;
    const int q0 = qb * 64;
    const int nt = qb + 1;

    const __half* Qg  = Q  + ((size_t)b*TQ + q0)*DMODEL + h*HDIM;
    const __half* Kg  = K  + (size_t)b*CACHE*DMODEL + h*HDIM;
    const __half* Vtg = Vt + (size_t)bh*HDIM*CACHE;

#pragma unroll
    for (int c = 0; c < 8; c++) {
        int id = tid + c*128;
        int row = id >> 4, seg = id & 15;
        cp_async16(smaddr + (AQS + row*QST + seg*4)*4,
                   Qg + (size_t)row*2048 + seg*8);
    }

    auto load_kv = [&](int it) {
        const int s = it & 1;
        const int kv0 = it * 64;
        const __half* Kt = Kg + (size_t)kv0*2048;
#pragma unroll
        for (int c = 0; c < 8; c++) {
            int id = tid + c*128;
            int row = id >> 4, seg = id & 15;
            cp_async16(smaddr + (AKS + s*AKSZ + row*QST + seg*4)*4,
                       Kt + (size_t)row*2048 + seg*8);
        }
#pragma unroll
        for (int c = 0; c < 8; c++) {
            int id = tid + c*128;
            int row = id >> 3, seg = id & 7;
            cp_async16(smaddr + (AVTS + s*AVSZ + row*VST + seg*4)*4,
                       Vtg + (size_t)row*CACHE + kv0 + seg*8);
        }
    };

    load_kv(0); CP_COMMIT();

    float m0 = -1e30f, m1 = -1e30f, l0 = 0.f, l1 = 0.f;
    float oacc[16][4];
#pragma unroll
    for (int nf = 0; nf < 16; nf++)
#pragma unroll
        for (int r = 0; r < 4; r++) oacc[nf][r] = 0.f;

    const int qrow0 = q0 + w*16 + lr;

    for (int i = 0; i < nt; i++) {
        CP_WAIT0();
        __syncthreads();
        if (i + 1 < nt) { load_kv(i + 1); CP_COMMIT(); }

        const uint32_t* Kb = sm + AKS + (i & 1)*AKSZ;
        const uint32_t* Qw = sm + AQS + (w*16)*QST;
        float sacc[8][4];
#pragma unroll
        for (int nf = 0; nf < 8; nf++)
#pragma unroll
            for (int r = 0; r < 4; r++) sacc[nf][r] = 0.f;

#pragma unroll
        for (int kb = 0; kb < 8; kb++) {
            const uint32_t* ap = Qw + lr*QST + kb*8 + lc;
            uint32_t a0 = ap[0];
            uint32_t a1 = ap[8*QST];
            uint32_t a2 = ap[4];
            uint32_t a3 = ap[8*QST + 4];
#pragma unroll
            for (int nf = 0; nf < 8; nf++) {
                const uint32_t* bp = Kb + (nf*8 + lr)*QST + kb*8 + lc;
                mma_f16(sacc[nf][0], sacc[nf][1], sacc[nf][2], sacc[nf][3],
                        a0, a1, a2, a3, bp[0], bp[4]);
            }
        }

        const int kvb = i*64;
        if (i == qb) {
#pragma unroll
            for (int nf = 0; nf < 8; nf++) {
                int col = kvb + nf*8 + 2*lc;
                if (col     > qrow0)     sacc[nf][0] = -1e30f;
                if (col + 1 > qrow0)     sacc[nf][1] = -1e30f;
                if (col     > qrow0 + 8) sacc[nf][2] = -1e30f;
                if (col + 1 > qrow0 + 8) sacc[nf][3] = -1e30f;
            }
        }

        float mx0 = -1e30f, mx1 = -1e30f;
#pragma unroll
        for (int nf = 0; nf < 8; nf++) {
            mx0 = fmaxf(mx0, fmaxf(sacc[nf][0], sacc[nf][1]));
            mx1 = fmaxf(mx1, fmaxf(sacc[nf][2], sacc[nf][3]));
        }
        mx0 = fmaxf(mx0, __shfl_xor_sync(0xffffffffu, mx0, 1));
        mx0 = fmaxf(mx0, __shfl_xor_sync(0xffffffffu, mx0, 2));
        mx1 = fmaxf(mx1, __shfl_xor_sync(0xffffffffu, mx1, 1));
        mx1 = fmaxf(mx1, __shfl_xor_sync(0xffffffffu, mx1, 2));
        float mn0 = fmaxf(m0, mx0), mn1 = fmaxf(m1, mx1);
        float al0 = __expf(m0 - mn0), al1 = __expf(m1 - mn1);
        m0 = mn0; m1 = mn1;

        uint32_t* Pw = sm + APS + (w*16)*VST;
        float rs0 = 0.f, rs1 = 0.f;
#pragma unroll
        for (int nf = 0; nf < 8; nf++) {
            float p0 = __expf(sacc[nf][0] - mn0);
            float p1 = __expf(sacc[nf][1] - mn0);
            float p2 = __expf(sacc[nf][2] - mn1);
            float p3 = __expf(sacc[nf][3] - mn1);
            rs0 += p0 + p1; rs1 += p2 + p3;
            __half2 h01 = __floats2half2_rn(p0, p1);
            __half2 h23 = __floats2half2_rn(p2, p3);
            Pw[lr*VST + nf*4 + lc]     = *(const uint32_t*)&h01;
            Pw[(lr+8)*VST + nf*4 + lc] = *(const uint32_t*)&h23;
        }
        rs0 += __shfl_xor_sync(0xffffffffu, rs0, 1);
        rs0 += __shfl_xor_sync(0xffffffffu, rs0, 2);
        rs1 += __shfl_xor_sync(0xffffffffu, rs1, 1);
        rs1 += __shfl_xor_sync(0xffffffffu, rs1, 2);
        l0 = l0*al0 + rs0; l1 = l1*al1 + rs1;
#pragma unroll
        for (int nf = 0; nf < 16; nf++) {
            oacc[nf][0] *= al0; oacc[nf][1] *= al0;
            oacc[nf][2] *= al1; oacc[nf][3] *= al1;
        }
        __syncwarp();

        const uint32_t* Vb = sm + AVTS + (i & 1)*AVSZ;
#pragma unroll
        for (int kb = 0; kb < 4; kb++) {
            const uint32_t* ap = Pw + lr*VST + kb*8 + lc;
            uint32_t a0 = ap[0];
            uint32_t a1 = ap[8*VST];
            uint32_t a2 = ap[4];
            uint32_t a3 = ap[8*VST + 4];
#pragma unroll
            for (int nf = 0; nf < 16; nf++) {
                const uint32_t* bp = Vb + (nf*8 + lr)*VST + kb*8 + lc;
                mma_f16(oacc[nf][0], oacc[nf][1], oacc[nf][2], oacc[nf][3],
                        a0, a1, a2, a3, bp[0], bp[4]);
            }
        }
    }

    float inv0 = 1.f / l0, inv1 = 1.f / l1;
    __half* Ob = O + ((size_t)b*TQ + q0 + w*16)*DMODEL + h*HDIM;
#pragma unroll
    for (int nf = 0; nf < 16; nf++) {
        int col = nf*8 + 2*lc;
        *(__half2*)(Ob + (size_t)lr*2048 + col) =
            __floats2half2_rn(oacc[nf][0]*inv0, oacc[nf][1]*inv0);
        *(__half2*)(Ob + (size_t)(lr+8)*2048 + col) =
            __floats2half2_rn(oacc[nf][2]*inv1, oacc[nf][3]*inv1);
    }
}

// ---------------------------------------------------------------------------
// new_k / new_v permute, cache half only, both tensors in one launch.
// ---------------------------------------------------------------------------
__global__ void permute_cache2(const float* __restrict__ cachek,
                               const float* __restrict__ cachev,
                               float* __restrict__ outk,
                               float* __restrict__ outv)
{
    const float* cache = blockIdx.y ? cachev : cachek;
    float* out = blockIdx.y ? outv : outk;
    int idx = blockIdx.x * blockDim.x + threadIdx.x;
    int j4  = idx & 511;
    int rem = idx >> 9;
    int ip  = rem & 1023;
    int b   = rem >> 10;
    int il  = ip & 63, ih = ip >> 6;
    int i   = (ih << 7) | il;
    int j   = j4 << 2;
    int t   = il*16 + (j >> 7);
    int c   = (ih << 7) | (j & 127);
    float4 v = *(const float4*)(cache + ((size_t)b*CACHE + t)*DMODEL + c);
    *(float4*)(out + (((size_t)((b << 11) | i)) << 11) + j) = v;
}

// ---------------------------------------------------------------------------
extern "C" void kernel_launch(void* const* d_in, const int* in_sizes, int n_in,
                              void* d_out, int out_size)
{
    const float* query  = (const float*)d_in[0];
    const float* key    = (const float*)d_in[1];
    const float* value  = (const float*)d_in[2];
    const float* cachek = (const float*)d_in[3];
    const float* cachev = (const float*)d_in[4];
    const float* Wq = (const float*)d_in[5];  const float* bq = (const float*)d_in[6];
    const float* Wk = (const float*)d_in[7];  const float* bk = (const float*)d_in[8];
    const float* Wv = (const float*)d_in[9];  const float* bv = (const float*)d_in[10];
    const float* Wo = (const float*)d_in[11]; const float* bo = (const float*)d_in[12];
    float* out = (float*)d_out;

    __half *qph, *ah, *qh, *kh, *vh, *ckh, *cvt, *wqh, *wkh, *wvh, *woh;
    cudaGetSymbolAddress((void**)&qph, g_qph);
    cudaGetSymbolAddress((void**)&ah,  g_attnh);
    cudaGetSymbolAddress((void**)&qh,  g_qh);
    cudaGetSymbolAddress((void**)&kh,  g_kh);
    cudaGetSymbolAddress((void**)&vh,  g_vh);
    cudaGetSymbolAddress((void**)&ckh, g_ckh);
    cudaGetSymbolAddress((void**)&cvt, g_cvt);
    cudaGetSymbolAddress((void**)&wqh, g_wqh);
    cudaGetSymbolAddress((void**)&wkh, g_wkh);
    cudaGetSymbolAddress((void**)&wvh, g_wvh);
    cudaGetSymbolAddress((void**)&woh, g_woh);

    // Fork resources (created per call; intentionally NOT destroyed — the
    // forked stream is still referenced by the in-progress graph capture,
    // and kernel_launch is only invoked twice: correctness + capture).
    cudaStream_t sB;
    cudaStreamCreateWithFlags(&sB, cudaStreamNonBlocking);
    cudaEvent_t eFork, eJoin;
    cudaEventCreateWithFlags(&eFork, cudaEventDisableTiming);
    cudaEventCreateWithFlags(&eJoin, cudaEventDisableTiming);

    cudaFuncSetAttribute(gemm_f16, cudaFuncAttributeMaxDynamicSharedMemorySize, GEMM_SMEM);
    cudaFuncSetAttribute(attn_mma, cudaFuncAttributeMaxDynamicSharedMemorySize,
                         ATTN_U32*4);

    // prep (default stream): fp16 conversions
    const int ACT8 = MROWS*DMODEL/8;        // 1048576
    const int W8   = DMODEL*DMODEL/8;       // 524288
    conv4_kernel<<<dim3(ACT8/256, 4), 256>>>(query, qh, key, kh, value, vh,
                                             cachek, ckh);
    conv4_kernel<<<dim3(W8/256, 4), 256>>>(Wq, wqh, Wk, wkh, Wv, wvh, Wo, woh);

    // ---- fork: branch B = K/V projections + cache permutes ----
    cudaEventRecord(eFork, 0);
    cudaStreamWaitEvent(sB, eFork, 0);

    GemmSet sk{kh, wkh, bk, out + NEWK_OFF, 1.f, 2};
    GemmSet sv{vh, wvh, bv, out + NEWV_OFF, 1.f, 2};
    gemm_f16<<<dim3(8, 32, 2), 256, GEMM_SMEM, sB>>>(sk, sv, sv);
    permute_cache2<<<dim3(2097152/256, 2), 256, 0, sB>>>(cachek, cachev,
                                                         out + NEWK_OFF, out + NEWV_OFF);

    // ---- branch A (default stream): Q proj -> attention -> O proj ----
    transpose_v_kernel<<<dim3(CACHE/32, HDIM/32, BB*NHEADS), dim3(32, 8)>>>(cachev, cvt);
    GemmSet sq{qh, wqh, bq, qph, INV_SCALE, 1};
    gemm_f16<<<dim3(8, 32, 1), 256, GEMM_SMEM>>>(sq, sq, sq);
    attn_mma<<<dim3(TQ/64, BB*NHEADS), 128, ATTN_U32*4>>>(qph, ckh, cvt, ah);
    GemmSet so{ah, woh, bo, out, 1.f, 0};
    gemm_f16<<<dim3(8, 32, 1), 256, GEMM_SMEM>>>(so, so, so);

    // ---- join ----
    cudaEventRecord(eJoin, sB);
    cudaStreamWaitEvent(0, eJoin, 0);
}

// round 14
// speedup vs baseline: 1.4996x; 1.4996x over previous
#include <cuda_runtime.h>
#include <cuda_fp16.h>
#include <math_constants.h>
#include <cstdint>

// Shapes
#define BB 4
#define TQ 1024
#define DMODEL 2048
#define NHEADS 16
#define HDIM 128
#define CACHE 1024
#define MROWS (BB*TQ)          // 4096
#define INV_SCALE 0.08838834764831843f  // 1/sqrt(128)

#define OUT_ELEMS   (BB*TQ*DMODEL)
#define NEWK_OFF    OUT_ELEMS
#define NEWV_OFF    (OUT_ELEMS + BB*2048*DMODEL)

// Scratch
__device__ __half g_qph  [MROWS*DMODEL];          // Q proj (fp16, pre-scaled)
__device__ __half g_attnh[MROWS*DMODEL];          // attention out (fp16)
__device__ __half g_qh [MROWS*DMODEL];            // fp16 activations
__device__ __half g_kh [MROWS*DMODEL];
__device__ __half g_vh [MROWS*DMODEL];
__device__ __half g_ckh[BB*CACHE*DMODEL];         // fp16 K cache [b][t][d]
__device__ __half g_cvt[BB*NHEADS*HDIM*CACHE];    // fp16 V cache transposed [bh][d][t]
__device__ __half g_wqh[DMODEL*DMODEL];           // fp16 weights
__device__ __half g_wkh[DMODEL*DMODEL];
__device__ __half g_wvh[DMODEL*DMODEL];
__device__ __half g_woh[DMODEL*DMODEL];

__device__ __forceinline__ uint32_t smem_u32(const void* p) {
    uint32_t a;
    asm("{ .reg .u64 t; cvta.to.shared.u64 t, %1; cvt.u32.u64 %0, t; }"
        : "=r"(a) : "l"(p));
    return a;
}
__device__ __forceinline__ void cp_async16(uint32_t dst, const void* src) {
    asm volatile("cp.async.cg.shared.global [%0], [%1], 16;" :: "r"(dst), "l"(src));
}
#define CP_COMMIT() asm volatile("cp.async.commit_group;" ::: "memory")
#define CP_WAIT1()  asm volatile("cp.async.wait_group 1;" ::: "memory")
#define CP_WAIT0()  asm volatile("cp.async.wait_group 0;" ::: "memory")

__device__ __forceinline__ void mma_f16(float& d0, float& d1, float& d2, float& d3,
                                        uint32_t a0, uint32_t a1, uint32_t a2, uint32_t a3,
                                        uint32_t b0, uint32_t b1)
{
    asm volatile(
        "mma.sync.aligned.m16n8k16.row.col.f32.f16.f16.f32 "
        "{%0,%1,%2,%3}, {%4,%5,%6,%7}, {%8,%9}, {%0,%1,%2,%3};"
        : "+f"(d0), "+f"(d1), "+f"(d2), "+f"(d3)
        : "r"(a0), "r"(a1), "r"(a2), "r"(a3), "r"(b0), "r"(b1));
}

// ===========================================================================
// prep kernels
// ===========================================================================
__global__ void conv4_kernel(const float* i0, __half* o0, const float* i1, __half* o1,
                             const float* i2, __half* o2, const float* i3, __half* o3)
{
    int idx = blockIdx.x * blockDim.x + threadIdx.x;
    const float* in; __half* out;
    switch (blockIdx.y) {
        case 0: in = i0; out = o0; break;
        case 1: in = i1; out = o1; break;
        case 2: in = i2; out = o2; break;
        default: in = i3; out = o3; break;
    }
    float4 v0 = ((const float4*)in)[2*idx];
    float4 v1 = ((const float4*)in)[2*idx+1];
    __half2 h[4];
    h[0] = __floats2half2_rn(v0.x, v0.y);
    h[1] = __floats2half2_rn(v0.z, v0.w);
    h[2] = __floats2half2_rn(v1.x, v1.y);
    h[3] = __floats2half2_rn(v1.z, v1.w);
    ((uint4*)out)[idx] = *(const uint4*)h;
}

// V cache: fp32 [b][t][2048] -> fp16 transposed per head [bh][d (128)][t (1024)]
__global__ void transpose_v_kernel(const float* __restrict__ cachev,
                                   __half* __restrict__ vt)
{
    __shared__ float tile[32][33];
    const int tx = threadIdx.x, ty = threadIdx.y;   // (32, 8)
    const int t0 = blockIdx.x * 32;
    const int d0 = blockIdx.y * 32;
    const int bh = blockIdx.z;
    const int b = bh >> 4, h = bh & 15;
#pragma unroll
    for (int dt = 0; dt < 4; dt++) {
        int t = t0 + ty + dt*8;
        tile[ty + dt*8][tx] =
            cachev[((size_t)b*CACHE + t)*DMODEL + h*HDIM + d0 + tx];
    }
    __syncthreads();
#pragma unroll
    for (int dt = 0; dt < 4; dt++) {
        int d = d0 + ty + dt*8;
        vt[(size_t)bh*HDIM*CACHE + (size_t)d*CACHE + t0 + tx] =
            __float2half_rn(tile[tx][ty + dt*8]);
    }
}

// ===========================================================================
// fp16 mma.sync GEMM: CTA 128x128, 128 threads, warp tile 64x64 (2x2 grid),
// BK=64, 3-stage cp.async, single barrier per k-iter, reg double-buffered
// fragments. 2 CTAs/SM (110 KB smem each) to hide barrier/wait latency.
// ===========================================================================
#define BK 64
#define STAGES 3
#define RS32 36
#define STAGE_ROWS 256                        // A 0..127, B 128..255
#define STAGE_U32 (STAGE_ROWS*RS32)           // 9216
#define STAGE_BYTES (STAGE_U32*4)             // 36864
#define GEMM_SMEM  (STAGES*STAGE_BYTES)       // 110592
#define NITERS (2048/BK)                      // 32

// out_mode: 0 = fp32 store, 1 = fp16 store (scaled), 2 = permuted fp32 scatter
struct GemmSet { const __half *A, *W; const float* bias; void *C; float scale; int out_mode; };

__global__ __launch_bounds__(128, 2)
void gemm_f16(GemmSet s0, GemmSet s1, GemmSet s2)
{
    const GemmSet& S = (blockIdx.z == 0) ? s0 : (blockIdx.z == 1) ? s1 : s2;
    const __half* __restrict__ A = S.A;
    const __half* __restrict__ W = S.W;
    const float* __restrict__ bias = S.bias;

    extern __shared__ __align__(128) uint32_t smem[];
    const uint32_t smem_addr = smem_u32(smem);
    const int tid  = threadIdx.x;
    const int wid  = tid >> 5;
    const int lane = tid & 31;
    const int bm = blockIdx.y * 128;
    const int bn = blockIdx.x * 128;
    const int wm = (wid & 1) * 64;
    const int wn = (wid >> 1) * 64;

    auto load_stage = [&](int it) {
        const int s  = (it < STAGES) ? it : (it % STAGES);
        const int k0 = it * BK;
        const uint32_t sbase = smem_addr + s * STAGE_BYTES;
        const __half* Ab = A + (size_t)bm * 2048 + k0;
        const __half* Wb = W + (size_t)bn * 2048 + k0;
#pragma unroll
        for (int c = 0; c < 8; c++) {            // A: 1024 x 16B chunks
            int id = tid + c * 128;
            int row = id >> 3, seg = id & 7;
            cp_async16(sbase + (row * RS32 + seg * 4) * 4,
                       Ab + (size_t)row * 2048 + seg * 8);
        }
#pragma unroll
        for (int c = 0; c < 8; c++) {            // B: 1024 x 16B chunks
            int id = tid + c * 128;
            int row = id >> 3, seg = id & 7;
            cp_async16(sbase + ((128 + row) * RS32 + seg * 4) * 4,
                       Wb + (size_t)row * 2048 + seg * 8);
        }
    };

    float acc[4][8][4];
#pragma unroll
    for (int mf = 0; mf < 4; mf++)
#pragma unroll
        for (int nf = 0; nf < 8; nf++)
#pragma unroll
            for (int r = 0; r < 4; r++) acc[mf][nf][r] = 0.f;

    load_stage(0); CP_COMMIT();
    load_stage(1); CP_COMMIT();

    const int lr = lane >> 2;
    const int lc = lane & 3;

    uint32_t afr[2][4][4], bfr[2][8][2];

    auto load_frags = [&](const uint32_t* As32, const uint32_t* Bs32, int ks,
                          uint32_t (&af)[4][4], uint32_t (&bf)[8][2]) {
        const int kb = ks * 8;
#pragma unroll
        for (int nf = 0; nf < 8; nf++) {
            const uint32_t* bp = Bs32 + (wn + nf*8 + lr) * RS32 + kb + lc;
            bf[nf][0] = bp[0];
            bf[nf][1] = bp[4];
        }
#pragma unroll
        for (int mf = 0; mf < 4; mf++) {
            const uint32_t* ap = As32 + (wm + mf*16 + lr) * RS32 + kb + lc;
            af[mf][0] = ap[0];
            af[mf][1] = ap[8*RS32];
            af[mf][2] = ap[4];
            af[mf][3] = ap[8*RS32 + 4];
        }
    };

    int buf = 0;
    for (int i = 0; i < NITERS; i++) {
        CP_WAIT1();               // stage i resident (1 prefetch outstanding)
        __syncthreads();          // everyone done reading buf (i-1)%3
        if (i + 2 < NITERS) load_stage(i + 2);   // writes buf (i+2)%3=(i-1)%3
        CP_COMMIT();              // uniform group count (empty near tail)

        const uint32_t* As32 = smem + (size_t)buf * STAGE_U32;
        const uint32_t* Bs32 = As32 + 128 * RS32;
        buf = (buf + 1 == STAGES) ? 0 : buf + 1;

        load_frags(As32, Bs32, 0, afr[0], bfr[0]);
#pragma unroll
        for (int ks = 0; ks < 4; ks++) {
            const int cur = ks & 1;
            if (ks < 3) load_frags(As32, Bs32, ks + 1, afr[cur^1], bfr[cur^1]);
#pragma unroll
            for (int mf = 0; mf < 4; mf++)
#pragma unroll
                for (int nf = 0; nf < 8; nf++)
                    mma_f16(acc[mf][nf][0], acc[mf][nf][1],
                            acc[mf][nf][2], acc[mf][nf][3],
                            afr[cur][mf][0], afr[cur][mf][1],
                            afr[cur][mf][2], afr[cur][mf][3],
                            bfr[cur][nf][0], bfr[cur][nf][1]);
        }
    }

    if (S.out_mode == 2) {
        float* C = (float*)S.C;
#pragma unroll
        for (int nf = 0; nf < 8; nf++) {
            const int col = bn + wn + nf*8 + lc*2;
            const float b0 = bias[col], b1 = bias[col + 1];
            const int ch = (col >> 7) << 7;
            const int cl = col & 127;
#pragma unroll
            for (int mf = 0; mf < 4; mf++) {
                const int row0 = bm + wm + mf*16 + lr;
#pragma unroll
                for (int rr = 0; rr < 2; rr++) {
                    const int row = row0 + rr*8;
                    const int bb = row >> 10, tq = row & 1023;
                    const int ii = ch | 64 | (tq >> 4);
                    const int jj = ((tq & 15) << 7) | cl;
                    *(float2*)(C + (((size_t)((bb << 11) | ii)) << 11) + jj) =
                        make_float2(acc[mf][nf][rr*2+0] + b0,
                                    acc[mf][nf][rr*2+1] + b1);
                }
            }
        }
    } else if (S.out_mode == 1) {
        __half* C = (__half*)S.C;
        const float scale = S.scale;
#pragma unroll
        for (int nf = 0; nf < 8; nf++) {
            const int col = bn + wn + nf*8 + lc*2;
            const float b0 = bias[col], b1 = bias[col + 1];
#pragma unroll
            for (int mf = 0; mf < 4; mf++) {
                const int row0 = bm + wm + mf*16 + lr;
                *(__half2*)(C + (size_t)row0 * 2048 + col) =
                    __floats2half2_rn((acc[mf][nf][0] + b0) * scale,
                                      (acc[mf][nf][1] + b1) * scale);
                *(__half2*)(C + (size_t)(row0 + 8) * 2048 + col) =
                    __floats2half2_rn((acc[mf][nf][2] + b0) * scale,
                                      (acc[mf][nf][3] + b1) * scale);
            }
        }
    } else {
        float* C = (float*)S.C;
#pragma unroll
        for (int nf = 0; nf < 8; nf++) {
            const int col = bn + wn + nf*8 + lc*2;
            const float b0 = bias[col], b1 = bias[col + 1];
#pragma unroll
            for (int mf = 0; mf < 4; mf++) {
                const int row0 = bm + wm + mf*16 + lr;
                *(float2*)(C + (size_t)row0 * 2048 + col) =
                    make_float2(acc[mf][nf][0] + b0, acc[mf][nf][1] + b1);
                *(float2*)(C + (size_t)(row0 + 8) * 2048 + col) =
                    make_float2(acc[mf][nf][2] + b0, acc[mf][nf][3] + b1);
            }
        }
    }
}

// ===========================================================================
// fp16 tensor-core flash attention, causal over cache only. (unchanged R11)
// ===========================================================================
#define QST 68
#define VST 36
#define AQS 0
#define AKS (64*QST)
#define AKSZ (64*QST)
#define AVTS (AKS + 2*AKSZ)
#define AVSZ (128*VST)
#define APS (AVTS + 2*AVSZ)
#define ATTN_U32 (APS + 64*VST)            // 24576 -> 98304 B

__global__ __launch_bounds__(128, 1)
void attn_mma(const __half* __restrict__ Q,
              const __half* __restrict__ K,
              const __half* __restrict__ Vt,
              __half* __restrict__ O)
{
    extern __shared__ __align__(128) uint32_t sm[];
    const uint32_t smaddr = smem_u32(sm);
    const int tid = threadIdx.x;
    const int w = tid >> 5, lane = tid & 31;
    const int lr = lane >> 2, lc = lane & 3;
    const int qb = gridDim.x - 1 - blockIdx.x;   // big tiles first
    const int bh = blockIdx.y;
    const int b = bh >> 4, h = bh & 15;
    const int q0 = qb * 64;
    const int nt = qb + 1;

    const __half* Qg  = Q  + ((size_t)b*TQ + q0)*DMODEL + h*HDIM;
    const __half* Kg  = K  + (size_t)b*CACHE*DMODEL + h*HDIM;
    const __half* Vtg = Vt + (size_t)bh*HDIM*CACHE;

#pragma unroll
    for (int c = 0; c < 8; c++) {
        int id = tid + c*128;
        int row = id >> 4, seg = id & 15;
        cp_async16(smaddr + (AQS + row*QST + seg*4)*4,
                   Qg + (size_t)row*2048 + seg*8);
    }

    auto load_kv = [&](int it) {
        const int s = it & 1;
        const int kv0 = it * 64;
        const __half* Kt = Kg + (size_t)kv0*2048;
#pragma unroll
        for (int c = 0; c < 8; c++) {
            int id = tid + c*128;
            int row = id >> 4, seg = id & 15;
            cp_async16(smaddr + (AKS + s*AKSZ + row*QST + seg*4)*4,
                       Kt + (size_t)row*2048 + seg*8);
        }
#pragma unroll
        for (int c = 0; c < 8; c++) {
            int id = tid + c*128;
            int row = id >> 3, seg = id & 7;
            cp_async16(smaddr + (AVTS + s*AVSZ + row*VST + seg*4)*4,
                       Vtg + (size_t)row*CACHE + kv0 + seg*8);
        }
    };

    load_kv(0); CP_COMMIT();

    float m0 = -1e30f, m1 = -1e30f, l0 = 0.f, l1 = 0.f;
    float oacc[16][4];
#pragma unroll
    for (int nf = 0; nf < 16; nf++)
#pragma unroll
        for (int r = 0; r < 4; r++) oacc[nf][r] = 0.f;

    const int qrow0 = q0 + w*16 + lr;

    for (int i = 0; i < nt; i++) {
        CP_WAIT0();
        __syncthreads();
        if (i + 1 < nt) { load_kv(i + 1); CP_COMMIT(); }

        const uint32_t* Kb = sm + AKS + (i & 1)*AKSZ;
        const uint32_t* Qw = sm + AQS + (w*16)*QST;
        float sacc[8][4];
#pragma unroll
        for (int nf = 0; nf < 8; nf++)
#pragma unroll
            for (int r = 0; r < 4; r++) sacc[nf][r] = 0.f;

#pragma unroll
        for (int kb = 0; kb < 8; kb++) {
            const uint32_t* ap = Qw + lr*QST + kb*8 + lc;
            uint32_t a0 = ap[0];
            uint32_t a1 = ap[8*QST];
            uint32_t a2 = ap[4];
            uint32_t a3 = ap[8*QST + 4];
#pragma unroll
            for (int nf = 0; nf < 8; nf++) {
                const uint32_t* bp = Kb + (nf*8 + lr)*QST + kb*8 + lc;
                mma_f16(sacc[nf][0], sacc[nf][1], sacc[nf][2], sacc[nf][3],
                        a0, a1, a2, a3, bp[0], bp[4]);
            }
        }

        const int kvb = i*64;
        if (i == qb) {
#pragma unroll
            for (int nf = 0; nf < 8; nf++) {
                int col = kvb + nf*8 + 2*lc;
                if (col     > qrow0)     sacc[nf][0] = -1e30f;
                if (col + 1 > qrow0)     sacc[nf][1] = -1e30f;
                if (col     > qrow0 + 8) sacc[nf][2] = -1e30f;
                if (col + 1 > qrow0 + 8) sacc[nf][3] = -1e30f;
            }
        }

        float mx0 = -1e30f, mx1 = -1e30f;
#pragma unroll
        for (int nf = 0; nf < 8; nf++) {
            mx0 = fmaxf(mx0, fmaxf(sacc[nf][0], sacc[nf][1]));
            mx1 = fmaxf(mx1, fmaxf(sacc[nf][2], sacc[nf][3]));
        }
        mx0 = fmaxf(mx0, __shfl_xor_sync(0xffffffffu, mx0, 1));
        mx0 = fmaxf(mx0, __shfl_xor_sync(0xffffffffu, mx0, 2));
        mx1 = fmaxf(mx1, __shfl_xor_sync(0xffffffffu, mx1, 1));
        mx1 = fmaxf(mx1, __shfl_xor_sync(0xffffffffu, mx1, 2));
        float mn0 = fmaxf(m0, mx0), mn1 = fmaxf(m1, mx1);
        float al0 = __expf(m0 - mn0), al1 = __expf(m1 - mn1);
        m0 = mn0; m1 = mn1;

        uint32_t* Pw = sm + APS + (w*16)*VST;
        float rs0 = 0.f, rs1 = 0.f;
#pragma unroll
        for (int nf = 0; nf < 8; nf++) {
            float p0 = __expf(sacc[nf][0] - mn0);
            float p1 = __expf(sacc[nf][1] - mn0);
            float p2 = __expf(sacc[nf][2] - mn1);
            float p3 = __expf(sacc[nf][3] - mn1);
            rs0 += p0 + p1; rs1 += p2 + p3;
            __half2 h01 = __floats2half2_rn(p0, p1);
            __half2 h23 = __floats2half2_rn(p2, p3);
            Pw[lr*VST + nf*4 + lc]     = *(const uint32_t*)&h01;
            Pw[(lr+8)*VST + nf*4 + lc] = *(const uint32_t*)&h23;
        }
        rs0 += __shfl_xor_sync(0xffffffffu, rs0, 1);
        rs0 += __shfl_xor_sync(0xffffffffu, rs0, 2);
        rs1 += __shfl_xor_sync(0xffffffffu, rs1, 1);
        rs1 += __shfl_xor_sync(0xffffffffu, rs1, 2);
        l0 = l0*al0 + rs0; l1 = l1*al1 + rs1;
#pragma unroll
        for (int nf = 0; nf < 16; nf++) {
            oacc[nf][0] *= al0; oacc[nf][1] *= al0;
            oacc[nf][2] *= al1; oacc[nf][3] *= al1;
        }
        __syncwarp();

        const uint32_t* Vb = sm + AVTS + (i & 1)*AVSZ;
#pragma unroll
        for (int kb = 0; kb < 4; kb++) {
            const uint32_t* ap = Pw + lr*VST + kb*8 + lc;
            uint32_t a0 = ap[0];
            uint32_t a1 = ap[8*VST];
            uint32_t a2 = ap[4];
            uint32_t a3 = ap[8*VST + 4];
#pragma unroll
            for (int nf = 0; nf < 16; nf++) {
                const uint32_t* bp = Vb + (nf*8 + lr)*VST + kb*8 + lc;
                mma_f16(oacc[nf][0], oacc[nf][1], oacc[nf][2], oacc[nf][3],
                        a0, a1, a2, a3, bp[0], bp[4]);
            }
        }
    }

    float inv0 = 1.f / l0, inv1 = 1.f / l1;
    __half* Ob = O + ((size_t)b*TQ + q0 + w*16)*DMODEL + h*HDIM;
#pragma unroll
    for (int nf = 0; nf < 16; nf++) {
        int col = nf*8 + 2*lc;
        *(__half2*)(Ob + (size_t)lr*2048 + col) =
            __floats2half2_rn(oacc[nf][0]*inv0, oacc[nf][1]*inv0);
        *(__half2*)(Ob + (size_t)(lr+8)*2048 + col) =
            __floats2half2_rn(oacc[nf][2]*inv1, oacc[nf][3]*inv1);
    }
}

// ---------------------------------------------------------------------------
// new_k / new_v permute, cache half only, both tensors in one launch.
// ---------------------------------------------------------------------------
__global__ void permute_cache2(const float* __restrict__ cachek,
                               const float* __restrict__ cachev,
                               float* __restrict__ outk,
                               float* __restrict__ outv)
{
    const float* cache = blockIdx.y ? cachev : cachek;
    float* out = blockIdx.y ? outv : outk;
    int idx = blockIdx.x * blockDim.x + threadIdx.x;
    int j4  = idx & 511;
    int rem = idx >> 9;
    int ip  = rem & 1023;
    int b   = rem >> 10;
    int il  = ip & 63, ih = ip >> 6;
    int i   = (ih << 7) | il;
    int j   = j4 << 2;
    int t   = il*16 + (j >> 7);
    int c   = (ih << 7) | (j & 127);
    float4 v = *(const float4*)(cache + ((size_t)b*CACHE + t)*DMODEL + c);
    *(float4*)(out + (((size_t)((b << 11) | i)) << 11) + j) = v;
}

// ---------------------------------------------------------------------------
extern "C" void kernel_launch(void* const* d_in, const int* in_sizes, int n_in,
                              void* d_out, int out_size)
{
    const float* query  = (const float*)d_in[0];
    const float* key    = (const float*)d_in[1];
    const float* value  = (const float*)d_in[2];
    const float* cachek = (const float*)d_in[3];
    const float* cachev = (const float*)d_in[4];
    const float* Wq = (const float*)d_in[5];  const float* bq = (const float*)d_in[6];
    const float* Wk = (const float*)d_in[7];  const float* bk = (const float*)d_in[8];
    const float* Wv = (const float*)d_in[9];  const float* bv = (const float*)d_in[10];
    const float* Wo = (const float*)d_in[11]; const float* bo = (const float*)d_in[12];
    float* out = (float*)d_out;

    __half *qph, *ah, *qh, *kh, *vh, *ckh, *cvt, *wqh, *wkh, *wvh, *woh;
    cudaGetSymbolAddress((void**)&qph, g_qph);
    cudaGetSymbolAddress((void**)&ah,  g_attnh);
    cudaGetSymbolAddress((void**)&qh,  g_qh);
    cudaGetSymbolAddress((void**)&kh,  g_kh);
    cudaGetSymbolAddress((void**)&vh,  g_vh);
    cudaGetSymbolAddress((void**)&ckh, g_ckh);
    cudaGetSymbolAddress((void**)&cvt, g_cvt);
    cudaGetSymbolAddress((void**)&wqh, g_wqh);
    cudaGetSymbolAddress((void**)&wkh, g_wkh);
    cudaGetSymbolAddress((void**)&wvh, g_wvh);
    cudaGetSymbolAddress((void**)&woh, g_woh);

    // prep: fp16 conversions + V transpose (serial, single stream)
    const int ACT8 = MROWS*DMODEL/8;        // 1048576
    const int W8   = DMODEL*DMODEL/8;       // 524288
    conv4_kernel<<<dim3(ACT8/256, 4), 256>>>(query, qh, key, kh, value, vh,
                                             cachek, ckh);
    conv4_kernel<<<dim3(W8/256, 4), 256>>>(Wq, wqh, Wk, wkh, Wv, wvh, Wo, woh);
    transpose_v_kernel<<<dim3(CACHE/32, HDIM/32, BB*NHEADS), dim3(32, 8)>>>(cachev, cvt);

    cudaFuncSetAttribute(gemm_f16, cudaFuncAttributeMaxDynamicSharedMemorySize, GEMM_SMEM);

    // merged QKV projections; Q -> fp16 pre-scaled, K/V scatter into new_k/new_v
    GemmSet sq{qh, wqh, bq, qph,             INV_SCALE, 1};
    GemmSet sk{kh, wkh, bk, out + NEWK_OFF,  1.f,       2};
    GemmSet sv{vh, wvh, bv, out + NEWV_OFF,  1.f,       2};
    gemm_f16<<<dim3(16, 32, 3), 128, GEMM_SMEM>>>(sq, sk, sv);

    cudaFuncSetAttribute(attn_mma, cudaFuncAttributeMaxDynamicSharedMemorySize,
                         ATTN_U32*4);
    attn_mma<<<dim3(TQ/64, BB*NHEADS), 128, ATTN_U32*4>>>(qph, ckh, cvt, ah);

    // O projection (fp16 A from attention)
    GemmSet so{ah, woh, bo, out, 1.f, 0};
    gemm_f16<<<dim3(16, 32, 1), 128, GEMM_SMEM>>>(so, so, so);

    // cache halves of new_k / new_v
    permute_cache2<<<dim3(2097152/256, 2), 256>>>(cachek, cachev,
                                                  out + NEWK_OFF, out + NEWV_OFF);
}